// round 7
// baseline (speedup 1.0000x reference)
#include <cuda_runtime.h>
#include <cstdint>

// Problem constants
#define BB      2
#define S_NEW   1024
#define S_CACHE 3072
#define S_TOT   4096
#define NH      16
#define DK      128
#define DM      2048
#define MROWS   (BB*S_NEW)   // 2048

// Scratch (device globals — no allocation allowed)
__device__ float g_q[BB*NH*S_NEW*DK];    // Q in [b,h,s,d]
__device__ float g_att[MROWS*DM];        // attention output in [b,s, h*dk]

// ---------------------------------------------------------------------------
// f32x2 helpers (packed dual-FMA; full-rate fp32 path on sm_103a)
// ---------------------------------------------------------------------------
__device__ __forceinline__ unsigned long long fma2(unsigned long long a,
                                                   unsigned long long b,
                                                   unsigned long long c) {
    unsigned long long d;
    asm("fma.rn.f32x2 %0, %1, %2, %3;" : "=l"(d) : "l"(a), "l"(b), "l"(c));
    return d;
}
__device__ __forceinline__ float2 unpk2(unsigned long long v) {
    float2 r;
    asm("mov.b64 {%0, %1}, %2;" : "=f"(r.x), "=f"(r.y) : "l"(v));
    return r;
}

// ---------------------------------------------------------------------------
// 1) Copy old cache rows into the updated-cache output region
//    src: [2,B,H,3072,128]   dst: [2,B,H,4096,128] (rows 0..3071)
// ---------------------------------------------------------------------------
__global__ void copy_cache_kernel(const float4* __restrict__ src,
                                  float4* __restrict__ dst) {
    int i = blockIdx.x * blockDim.x + threadIdx.x;
    const int per   = S_CACHE * DK / 4;        // 98304 float4 per (kv,b,h)
    const int total = 2 * BB * NH * per;
    if (i < total) {
        int c = i / per;
        int w = i - c * per;
        dst[(size_t)c * (S_TOT * DK / 4) + w] = src[i];
    }
}

// ---------------------------------------------------------------------------
// 2/4) Linear layer: Y = A @ W^T + bias.  128x128x16 tile, 256 thr, 8x8 micro,
//      FFMA2 inner loop with A duplicated in smem (zero packing MOVs).
//      mode==0: A=x, z=blockIdx.z selects Q/K/V; Q -> g_q, K/V -> cache slots.
//      mode==1: A=g_att, W0/B0 = Wo/bo, write outp directly.
// ---------------------------------------------------------------------------
__global__ __launch_bounds__(256, 2)
void linear_kernel(const float* __restrict__ A,
                   const float* __restrict__ W0, const float* __restrict__ B0,
                   const float* __restrict__ W1, const float* __restrict__ B1,
                   const float* __restrict__ W2, const float* __restrict__ B2,
                   float* __restrict__ cache_out, float* __restrict__ outp,
                   int mode) {
    __shared__ float As2[16][264];   // A duplicated: [k][2m], 8-float pad
    __shared__ float Bs [16][132];   // W transposed: [k][n],  4-float pad

    const int z = blockIdx.z;
    const float* Ap   = mode ? (const float*)g_att : A;
    const float* W    = (mode || z == 0) ? W0 : (z == 1 ? W1 : W2);
    const float* bias = (mode || z == 0) ? B0 : (z == 1 ? B1 : B2);

    const int m0 = blockIdx.y * 128, n0 = blockIdx.x * 128;
    const int tid = threadIdx.x;
    const int tx = tid & 15, ty = tid >> 4;

    unsigned long long acc[8][4];
#pragma unroll
    for (int i = 0; i < 8; i++)
#pragma unroll
        for (int j = 0; j < 4; j++) acc[i][j] = 0ull;

    for (int k0 = 0; k0 < DM; k0 += 16) {
#pragma unroll
        for (int it = 0; it < 2; ++it) {
            int id = tid + it * 256;          // 0..511
            int r  = id >> 2;                 // 0..127
            int kc = (id & 3) << 2;           // 0,4,8,12
            float4 a = *(const float4*)(Ap + (size_t)(m0 + r) * DM + k0 + kc);
            As2[kc + 0][2 * r] = a.x; As2[kc + 0][2 * r + 1] = a.x;
            As2[kc + 1][2 * r] = a.y; As2[kc + 1][2 * r + 1] = a.y;
            As2[kc + 2][2 * r] = a.z; As2[kc + 2][2 * r + 1] = a.z;
            As2[kc + 3][2 * r] = a.w; As2[kc + 3][2 * r + 1] = a.w;
            float4 w4 = *(const float4*)(W + (size_t)(n0 + r) * DM + k0 + kc);
            Bs[kc + 0][r] = w4.x; Bs[kc + 1][r] = w4.y;
            Bs[kc + 2][r] = w4.z; Bs[kc + 3][r] = w4.w;
        }
        __syncthreads();
#pragma unroll
        for (int k = 0; k < 16; k++) {
            ulonglong2 a01 = *(const ulonglong2*)(&As2[k][ty * 16]);
            ulonglong2 a23 = *(const ulonglong2*)(&As2[k][ty * 16 + 4]);
            ulonglong2 a45 = *(const ulonglong2*)(&As2[k][ty * 16 + 8]);
            ulonglong2 a67 = *(const ulonglong2*)(&As2[k][ty * 16 + 12]);
            ulonglong2 b03 = *(const ulonglong2*)(&Bs[k][tx * 8]);
            ulonglong2 b47 = *(const ulonglong2*)(&Bs[k][tx * 8 + 4]);
            unsigned long long ad[8] = {a01.x, a01.y, a23.x, a23.y,
                                        a45.x, a45.y, a67.x, a67.y};
            unsigned long long bp[4] = {b03.x, b03.y, b47.x, b47.y};
#pragma unroll
            for (int i = 0; i < 8; i++)
#pragma unroll
                for (int j = 0; j < 4; j++)
                    acc[i][j] = fma2(ad[i], bp[j], acc[i][j]);
        }
        __syncthreads();
    }

    // Epilogue: bias + scatter
#pragma unroll
    for (int i = 0; i < 8; i++) {
        int m  = m0 + ty * 8 + i;
        int bb = m >> 10, sp = m & 1023;
#pragma unroll
        for (int jp = 0; jp < 4; jp++) {
            float2 v = unpk2(acc[i][jp]);
#pragma unroll
            for (int e = 0; e < 2; e++) {
                int n = n0 + tx * 8 + jp * 2 + e;
                float val = (e ? v.y : v.x) + bias[n];
                if (mode) {
                    outp[(size_t)m * DM + n] = val;
                } else {
                    int hh = n >> 7, d = n & 127;
                    if (z == 0)
                        g_q[((size_t)(bb * NH + hh) * S_NEW + sp) * DK + d] = val;
                    else
                        cache_out[((size_t)(((z - 1) * BB + bb) * NH + hh) * S_TOT
                                   + S_CACHE + sp) * DK + d] = val;
                }
            }
        }
    }
}

// ---------------------------------------------------------------------------
// 3) Causal flash attention. One block = (b, h, 128-query tile).
//    BQ=128, BKT=64, 256 threads: S micro 8x4, O micro 8x8 (same m rows so
//    online-softmax rescale stays thread-local). exp2 domain softmax.
//    Reads K/V from the already-updated cache in d_out.
//    Masking matches reference triu(k=3072): key t allowed iff t <= 3071 + q.
// ---------------------------------------------------------------------------
#define FLASH_SMEM ((128*132 + 128*68 + 64*132 + 64*132) * 4)

__global__ __launch_bounds__(256, 1)
void flash_kernel(const float* __restrict__ cache_out) {
    extern __shared__ float smf[];
    float* Qs = smf;                 // [k=128][m pitch 132] (transposed)
    float* Ks = Qs + 128 * 132;      // [k=128][n pitch 68]  (transposed)
    float* Vs = Ks + 128 * 68;       // [j=64 ][d pitch 132]
    float* Ps = Vs + 64 * 132;       // [j=64 ][m pitch 132]

    const int qt = 7 - (int)blockIdx.x;      // longest-running tiles first
    const int h  = blockIdx.y;
    const int b  = blockIdx.z;
    const int q0 = qt << 7;
    const int tid = threadIdx.x;
    const int tx = tid & 15, ty = tid >> 4;

    const float* Qg = g_q + ((size_t)(b * NH + h) * S_NEW + q0) * DK;
    const float* Kg = cache_out + (size_t)(b * NH + h) * S_TOT * DK;
    const float* Vg = cache_out + (size_t)((BB + b) * NH + h) * S_TOT * DK;

    // Load Q tile transposed: Qs[k][m]
#pragma unroll
    for (int it = 0; it < 16; ++it) {
        int id = tid + it * 256;       // 0..4095
        int r  = id >> 5;              // 0..127
        int kc = (id & 31) << 2;       // 0..124
        float4 v = *(const float4*)(Qg + (size_t)r * DK + kc);
        Qs[(kc + 0) * 132 + r] = v.x;
        Qs[(kc + 1) * 132 + r] = v.y;
        Qs[(kc + 2) * 132 + r] = v.z;
        Qs[(kc + 3) * 132 + r] = v.w;
    }

    float Mrow[8], Lrow[8], O[8][8];
#pragma unroll
    for (int i = 0; i < 8; i++) {
        Mrow[i] = -1e30f; Lrow[i] = 0.f;
#pragma unroll
        for (int j = 0; j < 8; j++) O[i][j] = 0.f;
    }

    const float cs = 0.0883883476483184f * 1.4426950408889634f; // 1/sqrt(128)*log2e
    const int ntiles = 50 + 2 * qt;   // keys allowed up to 3071 + q0 + 127

    for (int kt = 0; kt < ntiles; ++kt) {
        __syncthreads();   // previous PV done (and Q tile visible on iter 0)
        const float* kp = Kg + (size_t)(kt * 64) * DK;
        const float* vp = Vg + (size_t)(kt * 64) * DK;
#pragma unroll
        for (int it = 0; it < 8; ++it) {
            int id = tid + it * 256;   // 0..2047
            int n  = id >> 5;          // 0..63
            int kc = (id & 31) << 2;
            float4 kv4 = *(const float4*)(kp + (size_t)n * DK + kc);
            Ks[(kc + 0) * 68 + n] = kv4.x;
            Ks[(kc + 1) * 68 + n] = kv4.y;
            Ks[(kc + 2) * 68 + n] = kv4.z;
            Ks[(kc + 3) * 68 + n] = kv4.w;
            *(float4*)(Vs + n * 132 + kc) = *(const float4*)(vp + (size_t)n * DK + kc);
        }
        __syncthreads();

        // S = Q @ K^T  (8x4 per thread)
        float s[8][4];
#pragma unroll
        for (int i = 0; i < 8; i++)
#pragma unroll
            for (int j = 0; j < 4; j++) s[i][j] = 0.f;

#pragma unroll 4
        for (int k = 0; k < 128; k++) {
            float4 a0 = *(const float4*)(Qs + k * 132 + (ty << 3));
            float4 a1 = *(const float4*)(Qs + k * 132 + (ty << 3) + 4);
            float4 b4 = *(const float4*)(Ks + k * 68 + (tx << 2));
            float av[8] = {a0.x, a0.y, a0.z, a0.w, a1.x, a1.y, a1.z, a1.w};
            float bv[4] = {b4.x, b4.y, b4.z, b4.w};
#pragma unroll
            for (int i = 0; i < 8; i++)
#pragma unroll
                for (int j = 0; j < 4; j++) s[i][j] += av[i] * bv[j];
        }

        // online softmax (exp2 domain)
        const bool domask = (kt * 64 + 63 >= S_CACHE + q0);
#pragma unroll
        for (int i = 0; i < 8; i++) {
            int m = (ty << 3) + i;
            float rmax = -1e30f;
#pragma unroll
            for (int j = 0; j < 4; j++) {
                float v = s[i][j] * cs;
                if (domask && (kt * 64 + (tx << 2) + j >= S_CACHE + q0 + m))
                    v = -1e30f;    // reference masks t >= 3072 + q (self included)
                s[i][j] = v;
                rmax = fmaxf(rmax, v);
            }
            rmax = fmaxf(rmax, __shfl_xor_sync(0xffffffffu, rmax, 8));
            rmax = fmaxf(rmax, __shfl_xor_sync(0xffffffffu, rmax, 4));
            rmax = fmaxf(rmax, __shfl_xor_sync(0xffffffffu, rmax, 2));
            rmax = fmaxf(rmax, __shfl_xor_sync(0xffffffffu, rmax, 1));
            float newM  = fmaxf(Mrow[i], rmax);
            float alpha = exp2f(Mrow[i] - newM);
            Mrow[i] = newM;
            float rs = 0.f;
#pragma unroll
            for (int j = 0; j < 4; j++) {
                float p = exp2f(s[i][j] - newM);
                rs += p;
                Ps[((tx << 2) + j) * 132 + m] = p;
            }
            rs += __shfl_xor_sync(0xffffffffu, rs, 8);
            rs += __shfl_xor_sync(0xffffffffu, rs, 4);
            rs += __shfl_xor_sync(0xffffffffu, rs, 2);
            rs += __shfl_xor_sync(0xffffffffu, rs, 1);
            Lrow[i] = Lrow[i] * alpha + rs;
#pragma unroll
            for (int j = 0; j < 8; j++) O[i][j] *= alpha;
        }
        __syncthreads();

        // O += P @ V  (8x8 per thread)
#pragma unroll 2
        for (int j = 0; j < 64; j++) {
            float4 p0 = *(const float4*)(Ps + j * 132 + (ty << 3));
            float4 p1 = *(const float4*)(Ps + j * 132 + (ty << 3) + 4);
            float4 v0 = *(const float4*)(Vs + j * 132 + (tx << 3));
            float4 v1 = *(const float4*)(Vs + j * 132 + (tx << 3) + 4);
            float pv[8] = {p0.x, p0.y, p0.z, p0.w, p1.x, p1.y, p1.z, p1.w};
            float vv[8] = {v0.x, v0.y, v0.z, v0.w, v1.x, v1.y, v1.z, v1.w};
#pragma unroll
            for (int i = 0; i < 8; i++)
#pragma unroll
                for (int d = 0; d < 8; d++) O[i][d] += pv[i] * vv[d];
        }
    }

    // normalize + write to g_att in [b, s, h*DK + d] layout
#pragma unroll
    for (int i = 0; i < 8; i++) {
        float inv = 1.f / Lrow[i];
        int m = q0 + (ty << 3) + i;
        float* dst = g_att + (size_t)(b * S_NEW + m) * DM + h * DK + (tx << 3);
        float4 o0 = make_float4(O[i][0] * inv, O[i][1] * inv, O[i][2] * inv, O[i][3] * inv);
        float4 o1 = make_float4(O[i][4] * inv, O[i][5] * inv, O[i][6] * inv, O[i][7] * inv);
        *(float4*)dst       = o0;
        *(float4*)(dst + 4) = o1;
    }
}

// ---------------------------------------------------------------------------
// Launch: out layout assumed = [out (B*S*DM floats)] ++ [cache_updated].
// ---------------------------------------------------------------------------
extern "C" void kernel_launch(void* const* d_in, const int* in_sizes, int n_in,
                              void* d_out, int out_size) {
    const float* x     = (const float*)d_in[0];
    const float* cache = (const float*)d_in[1];
    const float* Wq    = (const float*)d_in[2];
    const float* bq    = (const float*)d_in[3];
    const float* Wk    = (const float*)d_in[4];
    const float* bk    = (const float*)d_in[5];
    const float* Wv    = (const float*)d_in[6];
    const float* bv    = (const float*)d_in[7];
    const float* Wo    = (const float*)d_in[8];
    const float* bo    = (const float*)d_in[9];

    float* out       = (float*)d_out;
    float* cache_out = out + (size_t)BB * S_NEW * DM;   // 4,194,304 floats in

    // 1) copy old cache rows
    {
        int total  = 2 * BB * NH * (S_CACHE * DK / 4);
        int blocks = (total + 255) / 256;
        copy_cache_kernel<<<blocks, 256>>>((const float4*)cache, (float4*)cache_out);
    }

    // 2) fused QKV projections (z=0 Q, z=1 K, z=2 V)
    linear_kernel<<<dim3(16, 16, 3), 256>>>(x, Wq, bq, Wk, bk, Wv, bv,
                                            cache_out, nullptr, 0);

    // 3) flash attention (reads K/V from updated cache in d_out)
    cudaFuncSetAttribute(flash_kernel,
                         cudaFuncAttributeMaxDynamicSharedMemorySize, FLASH_SMEM);
    flash_kernel<<<dim3(8, NH, BB), 256, FLASH_SMEM>>>(cache_out);

    // 4) output projection
    linear_kernel<<<dim3(16, 16, 1), 256>>>(nullptr, Wo, bo,
                                            nullptr, nullptr, nullptr, nullptr,
                                            nullptr, out, 1);
}

// round 9
// speedup vs baseline: 1.6092x; 1.6092x over previous
#include <cuda_runtime.h>
#include <cstdint>

// Problem constants
#define BB      2
#define S_NEW   1024
#define S_CACHE 3072
#define S_TOT   4096
#define NH      16
#define DK      128
#define DM      2048

// Scratch (device globals — no allocation allowed)
__device__ float g_q[BB*NH*S_NEW*DK];    // Q in [b,h,s,d]
__device__ float g_att[BB*S_NEW*DM];     // attention output [b,s,h*dk] (tf32-rounded)
__device__ float g_xr[BB*S_NEW*DM];      // x rounded to tf32
__device__ float g_wr[4*DM*DM];          // Wq,Wk,Wv,Wo rounded to tf32

// ---------------------------------------------------------------------------
// helpers
// ---------------------------------------------------------------------------
__device__ __forceinline__ uint32_t smem_u32(const void* p) {
    uint32_t a;
    asm("{ .reg .u64 t; cvta.to.shared.u64 t, %1; cvt.u32.u64 %0, t; }"
        : "=r"(a) : "l"(p));
    return a;
}
__device__ __forceinline__ void cp16(uint32_t so, const void* gp) {
    asm volatile("cp.async.cg.shared.global [%0], [%1], 16;" :: "r"(so), "l"(gp));
}
__device__ __forceinline__ float rna_tf32(float x) {
    uint32_t u;
    asm("cvt.rna.tf32.f32 %0, %1;" : "=r"(u) : "f"(x));
    return __uint_as_float(u);
}

// D(16x8) += A(16x8,row) * B(8x8,col)  — tf32 tensor-core MMA (baseline PTX)
#define MMA8(c, a, b)                                                          \
    asm volatile("mma.sync.aligned.m16n8k8.row.col.f32.tf32.tf32.f32 "        \
        "{%0,%1,%2,%3}, {%4,%5,%6,%7}, {%8,%9}, {%0,%1,%2,%3};"               \
        : "+f"((c)[0]), "+f"((c)[1]), "+f"((c)[2]), "+f"((c)[3])              \
        : "r"((a)[0]), "r"((a)[1]), "r"((a)[2]), "r"((a)[3]),                 \
          "r"((b)[0]), "r"((b)[1]))

// ---------------------------------------------------------------------------
// 0) Round x and the four weight matrices to tf32 (RNA, unbiased) once.
//    Segments are 4M elements each (power of two) -> shift/mask indexing.
// ---------------------------------------------------------------------------
__global__ void round_kernel(const float* __restrict__ x,
                             const float* __restrict__ Wq,
                             const float* __restrict__ Wk,
                             const float* __restrict__ Wv,
                             const float* __restrict__ Wo) {
    const int SEG = DM * DM;                 // 4194304
    int i = blockIdx.x * blockDim.x + threadIdx.x;
    const int stride = gridDim.x * blockDim.x;
    for (; i < 5 * SEG; i += stride) {
        int seg = i >> 22, o = i & (SEG - 1);
        float v;
        float* dst;
        if (seg == 0)      { v = x[o];  dst = g_xr + o; }
        else               { const float* W = (seg == 1) ? Wq : (seg == 2) ? Wk
                                              : (seg == 3) ? Wv : Wo;
                             v = W[o]; dst = g_wr + (size_t)(seg - 1) * SEG + o; }
        *dst = rna_tf32(v);
    }
}

// ---------------------------------------------------------------------------
// 1) Copy old cache rows into the updated-cache output region
// ---------------------------------------------------------------------------
__global__ void copy_cache_kernel(const float4* __restrict__ src,
                                  float4* __restrict__ dst) {
    int i = blockIdx.x * blockDim.x + threadIdx.x;
    const int per   = S_CACHE * DK / 4;
    const int total = 2 * BB * NH * per;
    if (i < total) {
        int c = i / per;
        int w = i - c * per;
        dst[(size_t)c * (S_TOT * DK / 4) + w] = src[i];
    }
}

// ---------------------------------------------------------------------------
// 2/4) Tensor-core GEMM (mma.sync tf32): Y[M,N] = A[M,K] @ W[N,K]^T + bias.
//      128x128 block tile, 8 warps (2Mx4N), warp tile 64x32, KC=16,
//      double-buffered cp.async.
//      mode==0: A=g_xr, z picks Wq/Wk/Wv; Q->g_q, K/V->cache new slots.
//      mode==1: A=g_att, W=Wo -> outp.
// ---------------------------------------------------------------------------
#define KC    16
#define PITCH 20                 // row pitch in floats (16B-aligned, conflict-free)
#define NCH   (DM / KC)          // 128

__global__ __launch_bounds__(256, 2)
void gemm_mma_kernel(const float* __restrict__ B0,
                     const float* __restrict__ B1,
                     const float* __restrict__ B2,
                     float* __restrict__ cache_out,
                     float* __restrict__ outp,
                     int mode) {
    __shared__ __align__(16) float As[2][128 * PITCH];
    __shared__ __align__(16) float Bs[2][128 * PITCH];

    const int tid = threadIdx.x;
    const int warp = tid >> 5, lane = tid & 31;
    const int g = lane >> 2, t = lane & 3;
    const int z = blockIdx.z;

    const float* Ap = mode ? g_att : g_xr;
    const float* W  = g_wr + (size_t)(mode ? 3 : z) * DM * DM;
    const float* bias = mode ? B0 : (z == 0 ? B0 : (z == 1 ? B1 : B2));

    const int m0 = blockIdx.y * 128, n0 = blockIdx.x * 128;
    const int wm = (warp & 1) * 64, wn = (warp >> 1) * 32;

    const uint32_t sA = smem_u32(As);
    const uint32_t sB = smem_u32(Bs);

    float acc[4][4][4];
#pragma unroll
    for (int mt = 0; mt < 4; mt++)
#pragma unroll
        for (int nt = 0; nt < 4; nt++)
#pragma unroll
            for (int r = 0; r < 4; r++) acc[mt][nt][r] = 0.f;

    // chunk loader: chunk c -> buffer buf
    auto load = [&](int c, int buf) {
        const int k0 = c * KC;
        const uint32_t off = (uint32_t)buf * 128 * PITCH * 4;
#pragma unroll
        for (int i = 0; i < 2; i++) {
            int idx = tid + i * 256;        // 0..511
            int row = idx >> 2, c4 = idx & 3;
            cp16(sA + off + (row * PITCH + c4 * 4) * 4,
                 Ap + (size_t)(m0 + row) * DM + k0 + c4 * 4);
            cp16(sB + off + (row * PITCH + c4 * 4) * 4,
                 W + (size_t)(n0 + row) * DM + k0 + c4 * 4);
        }
        asm volatile("cp.async.commit_group;" ::: "memory");
    };

    load(0, 0);
    load(1, 1);

    for (int c = 0; c < NCH; ++c) {
        if (c + 1 < NCH) asm volatile("cp.async.wait_group 1;" ::: "memory");
        else             asm volatile("cp.async.wait_group 0;" ::: "memory");
        __syncthreads();

        const float* as = As[c & 1];
        const float* bs = Bs[c & 1];
#pragma unroll
        for (int ks = 0; ks < 2; ks++) {
            const int kb = ks * 8;
            uint32_t a[4][4], b[4][2];
#pragma unroll
            for (int mt = 0; mt < 4; mt++) {
                int r = wm + mt * 16 + g;
                a[mt][0] = __float_as_uint(as[r * PITCH + kb + t]);
                a[mt][1] = __float_as_uint(as[(r + 8) * PITCH + kb + t]);
                a[mt][2] = __float_as_uint(as[r * PITCH + kb + t + 4]);
                a[mt][3] = __float_as_uint(as[(r + 8) * PITCH + kb + t + 4]);
            }
#pragma unroll
            for (int nt = 0; nt < 4; nt++) {
                int cn = wn + nt * 8 + g;
                b[nt][0] = __float_as_uint(bs[cn * PITCH + kb + t]);
                b[nt][1] = __float_as_uint(bs[cn * PITCH + kb + t + 4]);
            }
#pragma unroll
            for (int mt = 0; mt < 4; mt++)
#pragma unroll
                for (int nt = 0; nt < 4; nt++)
                    MMA8(acc[mt][nt], a[mt], b[nt]);
        }
        __syncthreads();
        if (c + 2 < NCH) load(c + 2, c & 1);
    }

    // Epilogue: bias + scatter. c0,c1 -> (row g, cols 2t,2t+1); c2,c3 -> row g+8.
    const int hh = blockIdx.x;               // n-tile == one head (mode 0)
#pragma unroll
    for (int mt = 0; mt < 4; mt++) {
        int m = m0 + wm + mt * 16 + g;
        int bb = m >> 10, sp = m & 1023;
#pragma unroll
        for (int nt = 0; nt < 4; nt++) {
            int d = wn + nt * 8 + 2 * t;     // col within 128-wide tile
            int n = n0 + d;
            float b0v = __ldg(bias + n), b1v = __ldg(bias + n + 1);
            float2 v0 = make_float2(acc[mt][nt][0] + b0v, acc[mt][nt][1] + b1v);
            float2 v1 = make_float2(acc[mt][nt][2] + b0v, acc[mt][nt][3] + b1v);
            if (mode) {
                float* dst = outp + (size_t)m * DM + n;
                *(float2*)dst            = v0;
                *(float2*)(dst + 8 * DM) = v1;
            } else if (z == 0) {
                float* dst = g_q + ((size_t)(bb * NH + hh) * S_NEW + sp) * DK + d;
                *(float2*)dst            = v0;
                *(float2*)(dst + 8 * DK) = v1;
            } else {
                float* dst = cache_out
                    + ((size_t)(((z - 1) * BB + bb) * NH + hh) * S_TOT
                       + S_CACHE + sp) * DK + d;
                *(float2*)dst            = v0;
                *(float2*)(dst + 8 * DK) = v1;
            }
        }
    }
}

// ---------------------------------------------------------------------------
// 3) Causal flash attention (R6 passing version; epilogue RNA-rounds g_att).
// ---------------------------------------------------------------------------
#define FLASH_SMEM ((128*132 + 128*68 + 64*132 + 64*132) * 4)

__global__ __launch_bounds__(256, 1)
void flash_kernel(const float* __restrict__ cache_out) {
    extern __shared__ float smf[];
    float* Qs = smf;
    float* Ks = Qs + 128 * 132;
    float* Vs = Ks + 128 * 68;
    float* Ps = Vs + 64 * 132;

    const int qt = 7 - (int)blockIdx.x;
    const int h  = blockIdx.y;
    const int b  = blockIdx.z;
    const int q0 = qt << 7;
    const int tid = threadIdx.x;
    const int tx = tid & 15, ty = tid >> 4;

    const float* Qg = g_q + ((size_t)(b * NH + h) * S_NEW + q0) * DK;
    const float* Kg = cache_out + (size_t)(b * NH + h) * S_TOT * DK;
    const float* Vg = cache_out + (size_t)((BB + b) * NH + h) * S_TOT * DK;

#pragma unroll
    for (int it = 0; it < 16; ++it) {
        int id = tid + it * 256;
        int r  = id >> 5;
        int kc = (id & 31) << 2;
        float4 v = *(const float4*)(Qg + (size_t)r * DK + kc);
        Qs[(kc + 0) * 132 + r] = v.x;
        Qs[(kc + 1) * 132 + r] = v.y;
        Qs[(kc + 2) * 132 + r] = v.z;
        Qs[(kc + 3) * 132 + r] = v.w;
    }

    float Mrow[8], Lrow[8], O[8][8];
#pragma unroll
    for (int i = 0; i < 8; i++) {
        Mrow[i] = -1e30f; Lrow[i] = 0.f;
#pragma unroll
        for (int j = 0; j < 8; j++) O[i][j] = 0.f;
    }

    const float cs = 0.0883883476483184f * 1.4426950408889634f;
    const int ntiles = 50 + 2 * qt;

    for (int kt = 0; kt < ntiles; ++kt) {
        __syncthreads();
        const float* kp = Kg + (size_t)(kt * 64) * DK;
        const float* vp = Vg + (size_t)(kt * 64) * DK;
#pragma unroll
        for (int it = 0; it < 8; ++it) {
            int id = tid + it * 256;
            int n  = id >> 5;
            int kc = (id & 31) << 2;
            float4 kv4 = *(const float4*)(kp + (size_t)n * DK + kc);
            Ks[(kc + 0) * 68 + n] = kv4.x;
            Ks[(kc + 1) * 68 + n] = kv4.y;
            Ks[(kc + 2) * 68 + n] = kv4.z;
            Ks[(kc + 3) * 68 + n] = kv4.w;
            *(float4*)(Vs + n * 132 + kc) = *(const float4*)(vp + (size_t)n * DK + kc);
        }
        __syncthreads();

        float s[8][4];
#pragma unroll
        for (int i = 0; i < 8; i++)
#pragma unroll
            for (int j = 0; j < 4; j++) s[i][j] = 0.f;

#pragma unroll 4
        for (int k = 0; k < 128; k++) {
            float4 a0 = *(const float4*)(Qs + k * 132 + (ty << 3));
            float4 a1 = *(const float4*)(Qs + k * 132 + (ty << 3) + 4);
            float4 b4 = *(const float4*)(Ks + k * 68 + (tx << 2));
            float av[8] = {a0.x, a0.y, a0.z, a0.w, a1.x, a1.y, a1.z, a1.w};
            float bv[4] = {b4.x, b4.y, b4.z, b4.w};
#pragma unroll
            for (int i = 0; i < 8; i++)
#pragma unroll
                for (int j = 0; j < 4; j++) s[i][j] += av[i] * bv[j];
        }

        const bool domask = (kt * 64 + 63 >= S_CACHE + q0);
#pragma unroll
        for (int i = 0; i < 8; i++) {
            int m = (ty << 3) + i;
            float rmax = -1e30f;
#pragma unroll
            for (int j = 0; j < 4; j++) {
                float v = s[i][j] * cs;
                if (domask && (kt * 64 + (tx << 2) + j >= S_CACHE + q0 + m))
                    v = -1e30f;
                s[i][j] = v;
                rmax = fmaxf(rmax, v);
            }
            rmax = fmaxf(rmax, __shfl_xor_sync(0xffffffffu, rmax, 8));
            rmax = fmaxf(rmax, __shfl_xor_sync(0xffffffffu, rmax, 4));
            rmax = fmaxf(rmax, __shfl_xor_sync(0xffffffffu, rmax, 2));
            rmax = fmaxf(rmax, __shfl_xor_sync(0xffffffffu, rmax, 1));
            float newM  = fmaxf(Mrow[i], rmax);
            float alpha = exp2f(Mrow[i] - newM);
            Mrow[i] = newM;
            float rs = 0.f;
#pragma unroll
            for (int j = 0; j < 4; j++) {
                float p = exp2f(s[i][j] - newM);
                rs += p;
                Ps[((tx << 2) + j) * 132 + m] = p;
            }
            rs += __shfl_xor_sync(0xffffffffu, rs, 8);
            rs += __shfl_xor_sync(0xffffffffu, rs, 4);
            rs += __shfl_xor_sync(0xffffffffu, rs, 2);
            rs += __shfl_xor_sync(0xffffffffu, rs, 1);
            Lrow[i] = Lrow[i] * alpha + rs;
#pragma unroll
            for (int j = 0; j < 8; j++) O[i][j] *= alpha;
        }
        __syncthreads();

#pragma unroll 2
        for (int j = 0; j < 64; j++) {
            float4 p0 = *(const float4*)(Ps + j * 132 + (ty << 3));
            float4 p1 = *(const float4*)(Ps + j * 132 + (ty << 3) + 4);
            float4 v0 = *(const float4*)(Vs + j * 132 + (tx << 3));
            float4 v1 = *(const float4*)(Vs + j * 132 + (tx << 3) + 4);
            float pv[8] = {p0.x, p0.y, p0.z, p0.w, p1.x, p1.y, p1.z, p1.w};
            float vv[8] = {v0.x, v0.y, v0.z, v0.w, v1.x, v1.y, v1.z, v1.w};
#pragma unroll
            for (int i = 0; i < 8; i++)
#pragma unroll
                for (int d = 0; d < 8; d++) O[i][d] += pv[i] * vv[d];
        }
    }

    // normalize + RNA-round (A operand of out-proj) + write
#pragma unroll
    for (int i = 0; i < 8; i++) {
        float inv = 1.f / Lrow[i];
        int m = q0 + (ty << 3) + i;
        float* dst = g_att + (size_t)(b * S_NEW + m) * DM + h * DK + (tx << 3);
        float4 o0 = make_float4(rna_tf32(O[i][0] * inv), rna_tf32(O[i][1] * inv),
                                rna_tf32(O[i][2] * inv), rna_tf32(O[i][3] * inv));
        float4 o1 = make_float4(rna_tf32(O[i][4] * inv), rna_tf32(O[i][5] * inv),
                                rna_tf32(O[i][6] * inv), rna_tf32(O[i][7] * inv));
        *(float4*)dst       = o0;
        *(float4*)(dst + 4) = o1;
    }
}

// ---------------------------------------------------------------------------
// Launch
// ---------------------------------------------------------------------------
extern "C" void kernel_launch(void* const* d_in, const int* in_sizes, int n_in,
                              void* d_out, int out_size) {
    const float* x     = (const float*)d_in[0];
    const float* cache = (const float*)d_in[1];
    const float* Wq    = (const float*)d_in[2];
    const float* bq    = (const float*)d_in[3];
    const float* Wk    = (const float*)d_in[4];
    const float* bk    = (const float*)d_in[5];
    const float* Wv    = (const float*)d_in[6];
    const float* bv    = (const float*)d_in[7];
    const float* Wo    = (const float*)d_in[8];
    const float* bo    = (const float*)d_in[9];

    float* out       = (float*)d_out;
    float* cache_out = out + (size_t)BB * S_NEW * DM;

    // 0) round x + weights to tf32 (RNA)
    round_kernel<<<4096, 256>>>(x, Wq, Wk, Wv, Wo);

    // 1) copy old cache rows
    {
        int total  = 2 * BB * NH * (S_CACHE * DK / 4);
        int blocks = (total + 255) / 256;
        copy_cache_kernel<<<blocks, 256>>>((const float4*)cache, (float4*)cache_out);
    }

    // 2) fused QKV projections on tensor cores (z=0 Q, z=1 K, z=2 V)
    gemm_mma_kernel<<<dim3(16, 16, 3), 256>>>(bq, bk, bv, cache_out, nullptr, 0);

    // 3) flash attention (reads K/V from updated cache in d_out)
    cudaFuncSetAttribute(flash_kernel,
                         cudaFuncAttributeMaxDynamicSharedMemorySize, FLASH_SMEM);
    flash_kernel<<<dim3(8, NH, BB), 256, FLASH_SMEM>>>(cache_out);

    // 4) output projection on tensor cores
    gemm_mma_kernel<<<dim3(16, 16, 1), 256>>>(bo, nullptr, nullptr,
                                              nullptr, out, 1);
}

// round 10
// speedup vs baseline: 1.6118x; 1.0016x over previous
#include <cuda_runtime.h>
#include <cstdint>

// Problem constants
#define BB      2
#define S_NEW   1024
#define S_CACHE 3072
#define S_TOT   4096
#define NH      16
#define DK      128
#define DM      2048

// Scratch (device globals — no allocation allowed)
__device__ float g_q[BB*NH*S_NEW*DK];    // Q in [b,h,s,d]
__device__ float g_att[BB*S_NEW*DM];     // attention output [b,s,h*dk] (tf32-rounded)
__device__ float g_xr[BB*S_NEW*DM];      // x rounded to tf32
__device__ float g_wr[4*DM*DM];          // Wq,Wk,Wv,Wo rounded to tf32

// ---------------------------------------------------------------------------
// helpers
// ---------------------------------------------------------------------------
__device__ __forceinline__ uint32_t smem_u32(const void* p) {
    uint32_t a;
    asm("{ .reg .u64 t; cvta.to.shared.u64 t, %1; cvt.u32.u64 %0, t; }"
        : "=r"(a) : "l"(p));
    return a;
}
__device__ __forceinline__ void cp16(uint32_t so, const void* gp) {
    asm volatile("cp.async.cg.shared.global [%0], [%1], 16;" :: "r"(so), "l"(gp));
}
__device__ __forceinline__ float rna_tf32(float x) {
    uint32_t u;
    asm("cvt.rna.tf32.f32 %0, %1;" : "=r"(u) : "f"(x));
    return __uint_as_float(u);
}

// D(16x8) += A(16x8,row) * B(8x8,col)  — tf32 tensor-core MMA (baseline PTX)
#define MMA8(c, a, b)                                                          \
    asm volatile("mma.sync.aligned.m16n8k8.row.col.f32.tf32.tf32.f32 "        \
        "{%0,%1,%2,%3}, {%4,%5,%6,%7}, {%8,%9}, {%0,%1,%2,%3};"               \
        : "+f"((c)[0]), "+f"((c)[1]), "+f"((c)[2]), "+f"((c)[3])              \
        : "r"((a)[0]), "r"((a)[1]), "r"((a)[2]), "r"((a)[3]),                 \
          "r"((b)[0]), "r"((b)[1]))

// ---------------------------------------------------------------------------
// 0) Round x and the four weight matrices to tf32 (RNA, unbiased) once.
//    Segments are 4M elements each (power of two) -> shift/mask indexing.
// ---------------------------------------------------------------------------
__global__ void round_kernel(const float* __restrict__ x,
                             const float* __restrict__ Wq,
                             const float* __restrict__ Wk,
                             const float* __restrict__ Wv,
                             const float* __restrict__ Wo) {
    const int SEG = DM * DM;                 // 4194304
    int i = blockIdx.x * blockDim.x + threadIdx.x;
    const int stride = gridDim.x * blockDim.x;
    for (; i < 5 * SEG; i += stride) {
        int seg = i >> 22, o = i & (SEG - 1);
        float v;
        float* dst;
        if (seg == 0)      { v = x[o];  dst = g_xr + o; }
        else               { const float* W = (seg == 1) ? Wq : (seg == 2) ? Wk
                                              : (seg == 3) ? Wv : Wo;
                             v = W[o]; dst = g_wr + (size_t)(seg - 1) * SEG + o; }
        *dst = rna_tf32(v);
    }
}

// ---------------------------------------------------------------------------
// 1) Copy old cache rows into the updated-cache output region
// ---------------------------------------------------------------------------
__global__ void copy_cache_kernel(const float4* __restrict__ src,
                                  float4* __restrict__ dst) {
    int i = blockIdx.x * blockDim.x + threadIdx.x;
    const int per   = S_CACHE * DK / 4;
    const int total = 2 * BB * NH * per;
    if (i < total) {
        int c = i / per;
        int w = i - c * per;
        dst[(size_t)c * (S_TOT * DK / 4) + w] = src[i];
    }
}

// ---------------------------------------------------------------------------
// 2/4) Tensor-core GEMM (mma.sync tf32): Y[M,N] = A[M,K] @ W[N,K]^T + bias.
//      128x128 block tile, 8 warps (2Mx4N), warp tile 64x32, KC=16,
//      double-buffered cp.async.
//      mode==0: A=g_xr, z picks Wq/Wk/Wv; Q->g_q, K/V->cache new slots.
//      mode==1: A=g_att, W=Wo -> outp.
// ---------------------------------------------------------------------------
#define KC    16
#define PITCH 20                 // row pitch in floats (16B-aligned, conflict-free)
#define NCH   (DM / KC)          // 128

__global__ __launch_bounds__(256, 2)
void gemm_mma_kernel(const float* __restrict__ B0,
                     const float* __restrict__ B1,
                     const float* __restrict__ B2,
                     float* __restrict__ cache_out,
                     float* __restrict__ outp,
                     int mode) {
    __shared__ __align__(16) float As[2][128 * PITCH];
    __shared__ __align__(16) float Bs[2][128 * PITCH];

    const int tid = threadIdx.x;
    const int warp = tid >> 5, lane = tid & 31;
    const int g = lane >> 2, t = lane & 3;
    const int z = blockIdx.z;

    const float* Ap = mode ? g_att : g_xr;
    const float* W  = g_wr + (size_t)(mode ? 3 : z) * DM * DM;
    const float* bias = mode ? B0 : (z == 0 ? B0 : (z == 1 ? B1 : B2));

    const int m0 = blockIdx.y * 128, n0 = blockIdx.x * 128;
    const int wm = (warp & 1) * 64, wn = (warp >> 1) * 32;

    const uint32_t sA = smem_u32(As);
    const uint32_t sB = smem_u32(Bs);

    float acc[4][4][4];
#pragma unroll
    for (int mt = 0; mt < 4; mt++)
#pragma unroll
        for (int nt = 0; nt < 4; nt++)
#pragma unroll
            for (int r = 0; r < 4; r++) acc[mt][nt][r] = 0.f;

    // chunk loader: chunk c -> buffer buf
    auto load = [&](int c, int buf) {
        const int k0 = c * KC;
        const uint32_t off = (uint32_t)buf * 128 * PITCH * 4;
#pragma unroll
        for (int i = 0; i < 2; i++) {
            int idx = tid + i * 256;        // 0..511
            int row = idx >> 2, c4 = idx & 3;
            cp16(sA + off + (row * PITCH + c4 * 4) * 4,
                 Ap + (size_t)(m0 + row) * DM + k0 + c4 * 4);
            cp16(sB + off + (row * PITCH + c4 * 4) * 4,
                 W + (size_t)(n0 + row) * DM + k0 + c4 * 4);
        }
        asm volatile("cp.async.commit_group;" ::: "memory");
    };

    load(0, 0);
    load(1, 1);

    for (int c = 0; c < NCH; ++c) {
        if (c + 1 < NCH) asm volatile("cp.async.wait_group 1;" ::: "memory");
        else             asm volatile("cp.async.wait_group 0;" ::: "memory");
        __syncthreads();

        const float* as = As[c & 1];
        const float* bs = Bs[c & 1];
#pragma unroll
        for (int ks = 0; ks < 2; ks++) {
            const int kb = ks * 8;
            uint32_t a[4][4], b[4][2];
#pragma unroll
            for (int mt = 0; mt < 4; mt++) {
                int r = wm + mt * 16 + g;
                a[mt][0] = __float_as_uint(as[r * PITCH + kb + t]);
                a[mt][1] = __float_as_uint(as[(r + 8) * PITCH + kb + t]);
                a[mt][2] = __float_as_uint(as[r * PITCH + kb + t + 4]);
                a[mt][3] = __float_as_uint(as[(r + 8) * PITCH + kb + t + 4]);
            }
#pragma unroll
            for (int nt = 0; nt < 4; nt++) {
                int cn = wn + nt * 8 + g;
                b[nt][0] = __float_as_uint(bs[cn * PITCH + kb + t]);
                b[nt][1] = __float_as_uint(bs[cn * PITCH + kb + t + 4]);
            }
#pragma unroll
            for (int mt = 0; mt < 4; mt++)
#pragma unroll
                for (int nt = 0; nt < 4; nt++)
                    MMA8(acc[mt][nt], a[mt], b[nt]);
        }
        __syncthreads();
        if (c + 2 < NCH) load(c + 2, c & 1);
    }

    // Epilogue: bias + scatter. c0,c1 -> (row g, cols 2t,2t+1); c2,c3 -> row g+8.
    const int hh = blockIdx.x;               // n-tile == one head (mode 0)
#pragma unroll
    for (int mt = 0; mt < 4; mt++) {
        int m = m0 + wm + mt * 16 + g;
        int bb = m >> 10, sp = m & 1023;
#pragma unroll
        for (int nt = 0; nt < 4; nt++) {
            int d = wn + nt * 8 + 2 * t;     // col within 128-wide tile
            int n = n0 + d;
            float b0v = __ldg(bias + n), b1v = __ldg(bias + n + 1);
            float2 v0 = make_float2(acc[mt][nt][0] + b0v, acc[mt][nt][1] + b1v);
            float2 v1 = make_float2(acc[mt][nt][2] + b0v, acc[mt][nt][3] + b1v);
            if (mode) {
                float* dst = outp + (size_t)m * DM + n;
                *(float2*)dst            = v0;
                *(float2*)(dst + 8 * DM) = v1;
            } else if (z == 0) {
                float* dst = g_q + ((size_t)(bb * NH + hh) * S_NEW + sp) * DK + d;
                *(float2*)dst            = v0;
                *(float2*)(dst + 8 * DK) = v1;
            } else {
                float* dst = cache_out
                    + ((size_t)(((z - 1) * BB + bb) * NH + hh) * S_TOT
                       + S_CACHE + sp) * DK + d;
                *(float2*)dst            = v0;
                *(float2*)(dst + 8 * DK) = v1;
            }
        }
    }
}

// ---------------------------------------------------------------------------
// 3) Causal flash attention (R6 passing version; epilogue RNA-rounds g_att).
// ---------------------------------------------------------------------------
#define FLASH_SMEM ((128*132 + 128*68 + 64*132 + 64*132) * 4)

__global__ __launch_bounds__(256, 1)
void flash_kernel(const float* __restrict__ cache_out) {
    extern __shared__ float smf[];
    float* Qs = smf;
    float* Ks = Qs + 128 * 132;
    float* Vs = Ks + 128 * 68;
    float* Ps = Vs + 64 * 132;

    const int qt = 7 - (int)blockIdx.x;
    const int h  = blockIdx.y;
    const int b  = blockIdx.z;
    const int q0 = qt << 7;
    const int tid = threadIdx.x;
    const int tx = tid & 15, ty = tid >> 4;

    const float* Qg = g_q + ((size_t)(b * NH + h) * S_NEW + q0) * DK;
    const float* Kg = cache_out + (size_t)(b * NH + h) * S_TOT * DK;
    const float* Vg = cache_out + (size_t)((BB + b) * NH + h) * S_TOT * DK;

#pragma unroll
    for (int it = 0; it < 16; ++it) {
        int id = tid + it * 256;
        int r  = id >> 5;
        int kc = (id & 31) << 2;
        float4 v = *(const float4*)(Qg + (size_t)r * DK + kc);
        Qs[(kc + 0) * 132 + r] = v.x;
        Qs[(kc + 1) * 132 + r] = v.y;
        Qs[(kc + 2) * 132 + r] = v.z;
        Qs[(kc + 3) * 132 + r] = v.w;
    }

    float Mrow[8], Lrow[8], O[8][8];
#pragma unroll
    for (int i = 0; i < 8; i++) {
        Mrow[i] = -1e30f; Lrow[i] = 0.f;
#pragma unroll
        for (int j = 0; j < 8; j++) O[i][j] = 0.f;
    }

    const float cs = 0.0883883476483184f * 1.4426950408889634f;
    const int ntiles = 50 + 2 * qt;

    for (int kt = 0; kt < ntiles; ++kt) {
        __syncthreads();
        const float* kp = Kg + (size_t)(kt * 64) * DK;
        const float* vp = Vg + (size_t)(kt * 64) * DK;
#pragma unroll
        for (int it = 0; it < 8; ++it) {
            int id = tid + it * 256;
            int n  = id >> 5;
            int kc = (id & 31) << 2;
            float4 kv4 = *(const float4*)(kp + (size_t)n * DK + kc);
            Ks[(kc + 0) * 68 + n] = kv4.x;
            Ks[(kc + 1) * 68 + n] = kv4.y;
            Ks[(kc + 2) * 68 + n] = kv4.z;
            Ks[(kc + 3) * 68 + n] = kv4.w;
            *(float4*)(Vs + n * 132 + kc) = *(const float4*)(vp + (size_t)n * DK + kc);
        }
        __syncthreads();

        float s[8][4];
#pragma unroll
        for (int i = 0; i < 8; i++)
#pragma unroll
            for (int j = 0; j < 4; j++) s[i][j] = 0.f;

#pragma unroll 4
        for (int k = 0; k < 128; k++) {
            float4 a0 = *(const float4*)(Qs + k * 132 + (ty << 3));
            float4 a1 = *(const float4*)(Qs + k * 132 + (ty << 3) + 4);
            float4 b4 = *(const float4*)(Ks + k * 68 + (tx << 2));
            float av[8] = {a0.x, a0.y, a0.z, a0.w, a1.x, a1.y, a1.z, a1.w};
            float bv[4] = {b4.x, b4.y, b4.z, b4.w};
#pragma unroll
            for (int i = 0; i < 8; i++)
#pragma unroll
                for (int j = 0; j < 4; j++) s[i][j] += av[i] * bv[j];
        }

        const bool domask = (kt * 64 + 63 >= S_CACHE + q0);
#pragma unroll
        for (int i = 0; i < 8; i++) {
            int m = (ty << 3) + i;
            float rmax = -1e30f;
#pragma unroll
            for (int j = 0; j < 4; j++) {
                float v = s[i][j] * cs;
                if (domask && (kt * 64 + (tx << 2) + j >= S_CACHE + q0 + m))
                    v = -1e30f;
                s[i][j] = v;
                rmax = fmaxf(rmax, v);
            }
            rmax = fmaxf(rmax, __shfl_xor_sync(0xffffffffu, rmax, 8));
            rmax = fmaxf(rmax, __shfl_xor_sync(0xffffffffu, rmax, 4));
            rmax = fmaxf(rmax, __shfl_xor_sync(0xffffffffu, rmax, 2));
            rmax = fmaxf(rmax, __shfl_xor_sync(0xffffffffu, rmax, 1));
            float newM  = fmaxf(Mrow[i], rmax);
            float alpha = exp2f(Mrow[i] - newM);
            Mrow[i] = newM;
            float rs = 0.f;
#pragma unroll
            for (int j = 0; j < 4; j++) {
                float p = exp2f(s[i][j] - newM);
                rs += p;
                Ps[((tx << 2) + j) * 132 + m] = p;
            }
            rs += __shfl_xor_sync(0xffffffffu, rs, 8);
            rs += __shfl_xor_sync(0xffffffffu, rs, 4);
            rs += __shfl_xor_sync(0xffffffffu, rs, 2);
            rs += __shfl_xor_sync(0xffffffffu, rs, 1);
            Lrow[i] = Lrow[i] * alpha + rs;
#pragma unroll
            for (int j = 0; j < 8; j++) O[i][j] *= alpha;
        }
        __syncthreads();

#pragma unroll 2
        for (int j = 0; j < 64; j++) {
            float4 p0 = *(const float4*)(Ps + j * 132 + (ty << 3));
            float4 p1 = *(const float4*)(Ps + j * 132 + (ty << 3) + 4);
            float4 v0 = *(const float4*)(Vs + j * 132 + (tx << 3));
            float4 v1 = *(const float4*)(Vs + j * 132 + (tx << 3) + 4);
            float pv[8] = {p0.x, p0.y, p0.z, p0.w, p1.x, p1.y, p1.z, p1.w};
            float vv[8] = {v0.x, v0.y, v0.z, v0.w, v1.x, v1.y, v1.z, v1.w};
#pragma unroll
            for (int i = 0; i < 8; i++)
#pragma unroll
                for (int d = 0; d < 8; d++) O[i][d] += pv[i] * vv[d];
        }
    }

    // normalize + RNA-round (A operand of out-proj) + write
#pragma unroll
    for (int i = 0; i < 8; i++) {
        float inv = 1.f / Lrow[i];
        int m = q0 + (ty << 3) + i;
        float* dst = g_att + (size_t)(b * S_NEW + m) * DM + h * DK + (tx << 3);
        float4 o0 = make_float4(rna_tf32(O[i][0] * inv), rna_tf32(O[i][1] * inv),
                                rna_tf32(O[i][2] * inv), rna_tf32(O[i][3] * inv));
        float4 o1 = make_float4(rna_tf32(O[i][4] * inv), rna_tf32(O[i][5] * inv),
                                rna_tf32(O[i][6] * inv), rna_tf32(O[i][7] * inv));
        *(float4*)dst       = o0;
        *(float4*)(dst + 4) = o1;
    }
}

// ---------------------------------------------------------------------------
// Launch
// ---------------------------------------------------------------------------
extern "C" void kernel_launch(void* const* d_in, const int* in_sizes, int n_in,
                              void* d_out, int out_size) {
    const float* x     = (const float*)d_in[0];
    const float* cache = (const float*)d_in[1];
    const float* Wq    = (const float*)d_in[2];
    const float* bq    = (const float*)d_in[3];
    const float* Wk    = (const float*)d_in[4];
    const float* bk    = (const float*)d_in[5];
    const float* Wv    = (const float*)d_in[6];
    const float* bv    = (const float*)d_in[7];
    const float* Wo    = (const float*)d_in[8];
    const float* bo    = (const float*)d_in[9];

    float* out       = (float*)d_out;
    float* cache_out = out + (size_t)BB * S_NEW * DM;

    // 0) round x + weights to tf32 (RNA)
    round_kernel<<<4096, 256>>>(x, Wq, Wk, Wv, Wo);

    // 1) copy old cache rows
    {
        int total  = 2 * BB * NH * (S_CACHE * DK / 4);
        int blocks = (total + 255) / 256;
        copy_cache_kernel<<<blocks, 256>>>((const float4*)cache, (float4*)cache_out);
    }

    // 2) fused QKV projections on tensor cores (z=0 Q, z=1 K, z=2 V)
    gemm_mma_kernel<<<dim3(16, 16, 3), 256>>>(bq, bk, bv, cache_out, nullptr, 0);

    // 3) flash attention (reads K/V from updated cache in d_out)
    cudaFuncSetAttribute(flash_kernel,
                         cudaFuncAttributeMaxDynamicSharedMemorySize, FLASH_SMEM);
    flash_kernel<<<dim3(8, NH, BB), 256, FLASH_SMEM>>>(cache_out);

    // 4) output projection on tensor cores
    gemm_mma_kernel<<<dim3(16, 16, 1), 256>>>(bo, nullptr, nullptr,
                                              nullptr, out, 1);
}

// round 11
// speedup vs baseline: 1.6155x; 1.0022x over previous
#include <cuda_runtime.h>
#include <cstdint>

// Problem constants
#define BB      2
#define S_NEW   1024
#define S_CACHE 3072
#define S_TOT   4096
#define NH      16
#define DK      128
#define DM      2048

// Scratch (device globals — no allocation allowed)
__device__ float g_q[BB*NH*S_NEW*DK];    // Q in [b,h,s,d]
__device__ float g_att[BB*S_NEW*DM];     // attention output [b,s,h*dk] (tf32-rounded)
__device__ float g_xr[BB*S_NEW*DM];      // x rounded to tf32
__device__ float g_wr[4*DM*DM];          // Wq,Wk,Wv,Wo rounded to tf32

// ---------------------------------------------------------------------------
// helpers
// ---------------------------------------------------------------------------
__device__ __forceinline__ uint32_t smem_u32(const void* p) {
    uint32_t a;
    asm("{ .reg .u64 t; cvta.to.shared.u64 t, %1; cvt.u32.u64 %0, t; }"
        : "=r"(a) : "l"(p));
    return a;
}
__device__ __forceinline__ void cp16(uint32_t so, const void* gp) {
    asm volatile("cp.async.cg.shared.global [%0], [%1], 16;" :: "r"(so), "l"(gp));
}
__device__ __forceinline__ float rna_tf32(float x) {
    uint32_t u;
    asm("cvt.rna.tf32.f32 %0, %1;" : "=r"(u) : "f"(x));
    return __uint_as_float(u);
}

// D(16x8) += A(16x8,row) * B(8x8,col)  — tf32 tensor-core MMA (baseline PTX)
#define MMA8(c, a, b)                                                          \
    asm volatile("mma.sync.aligned.m16n8k8.row.col.f32.tf32.tf32.f32 "        \
        "{%0,%1,%2,%3}, {%4,%5,%6,%7}, {%8,%9}, {%0,%1,%2,%3};"               \
        : "+f"((c)[0]), "+f"((c)[1]), "+f"((c)[2]), "+f"((c)[3])              \
        : "r"((a)[0]), "r"((a)[1]), "r"((a)[2]), "r"((a)[3]),                 \
          "r"((b)[0]), "r"((b)[1]))

// ---------------------------------------------------------------------------
// 0) Round x and the four weight matrices to tf32 (RNA, unbiased) once.
//    Segments are 4M elements each (power of two) -> shift/mask indexing.
// ---------------------------------------------------------------------------
__global__ void round_kernel(const float* __restrict__ x,
                             const float* __restrict__ Wq,
                             const float* __restrict__ Wk,
                             const float* __restrict__ Wv,
                             const float* __restrict__ Wo) {
    const int SEG = DM * DM;                 // 4194304
    int i = blockIdx.x * blockDim.x + threadIdx.x;
    const int stride = gridDim.x * blockDim.x;
    for (; i < 5 * SEG; i += stride) {
        int seg = i >> 22, o = i & (SEG - 1);
        float v;
        float* dst;
        if (seg == 0)      { v = x[o];  dst = g_xr + o; }
        else               { const float* W = (seg == 1) ? Wq : (seg == 2) ? Wk
                                              : (seg == 3) ? Wv : Wo;
                             v = W[o]; dst = g_wr + (size_t)(seg - 1) * SEG + o; }
        *dst = rna_tf32(v);
    }
}

// ---------------------------------------------------------------------------
// 1) Copy old cache rows into the updated-cache output region
// ---------------------------------------------------------------------------
__global__ void copy_cache_kernel(const float4* __restrict__ src,
                                  float4* __restrict__ dst) {
    int i = blockIdx.x * blockDim.x + threadIdx.x;
    const int per   = S_CACHE * DK / 4;
    const int total = 2 * BB * NH * per;
    if (i < total) {
        int c = i / per;
        int w = i - c * per;
        dst[(size_t)c * (S_TOT * DK / 4) + w] = src[i];
    }
}

// ---------------------------------------------------------------------------
// 2/4) Tensor-core GEMM (mma.sync tf32): Y[M,N] = A[M,K] @ W[N,K]^T + bias.
//      128x128 block tile, 8 warps (2Mx4N), warp tile 64x32, KC=16,
//      double-buffered cp.async.
//      mode==0: A=g_xr, z picks Wq/Wk/Wv; Q->g_q, K/V->cache new slots.
//      mode==1: A=g_att, W=Wo -> outp.
// ---------------------------------------------------------------------------
#define KC    16
#define PITCH 20                 // row pitch in floats (16B-aligned, conflict-free)
#define NCH   (DM / KC)          // 128

__global__ __launch_bounds__(256, 2)
void gemm_mma_kernel(const float* __restrict__ B0,
                     const float* __restrict__ B1,
                     const float* __restrict__ B2,
                     float* __restrict__ cache_out,
                     float* __restrict__ outp,
                     int mode) {
    __shared__ __align__(16) float As[2][128 * PITCH];
    __shared__ __align__(16) float Bs[2][128 * PITCH];

    const int tid = threadIdx.x;
    const int warp = tid >> 5, lane = tid & 31;
    const int g = lane >> 2, t = lane & 3;
    const int z = blockIdx.z;

    const float* Ap = mode ? g_att : g_xr;
    const float* W  = g_wr + (size_t)(mode ? 3 : z) * DM * DM;
    const float* bias = mode ? B0 : (z == 0 ? B0 : (z == 1 ? B1 : B2));

    const int m0 = blockIdx.y * 128, n0 = blockIdx.x * 128;
    const int wm = (warp & 1) * 64, wn = (warp >> 1) * 32;

    const uint32_t sA = smem_u32(As);
    const uint32_t sB = smem_u32(Bs);

    float acc[4][4][4];
#pragma unroll
    for (int mt = 0; mt < 4; mt++)
#pragma unroll
        for (int nt = 0; nt < 4; nt++)
#pragma unroll
            for (int r = 0; r < 4; r++) acc[mt][nt][r] = 0.f;

    // chunk loader: chunk c -> buffer buf
    auto load = [&](int c, int buf) {
        const int k0 = c * KC;
        const uint32_t off = (uint32_t)buf * 128 * PITCH * 4;
#pragma unroll
        for (int i = 0; i < 2; i++) {
            int idx = tid + i * 256;        // 0..511
            int row = idx >> 2, c4 = idx & 3;
            cp16(sA + off + (row * PITCH + c4 * 4) * 4,
                 Ap + (size_t)(m0 + row) * DM + k0 + c4 * 4);
            cp16(sB + off + (row * PITCH + c4 * 4) * 4,
                 W + (size_t)(n0 + row) * DM + k0 + c4 * 4);
        }
        asm volatile("cp.async.commit_group;" ::: "memory");
    };

    load(0, 0);
    load(1, 1);

    for (int c = 0; c < NCH; ++c) {
        if (c + 1 < NCH) asm volatile("cp.async.wait_group 1;" ::: "memory");
        else             asm volatile("cp.async.wait_group 0;" ::: "memory");
        __syncthreads();

        const float* as = As[c & 1];
        const float* bs = Bs[c & 1];
#pragma unroll
        for (int ks = 0; ks < 2; ks++) {
            const int kb = ks * 8;
            uint32_t a[4][4], b[4][2];
#pragma unroll
            for (int mt = 0; mt < 4; mt++) {
                int r = wm + mt * 16 + g;
                a[mt][0] = __float_as_uint(as[r * PITCH + kb + t]);
                a[mt][1] = __float_as_uint(as[(r + 8) * PITCH + kb + t]);
                a[mt][2] = __float_as_uint(as[r * PITCH + kb + t + 4]);
                a[mt][3] = __float_as_uint(as[(r + 8) * PITCH + kb + t + 4]);
            }
#pragma unroll
            for (int nt = 0; nt < 4; nt++) {
                int cn = wn + nt * 8 + g;
                b[nt][0] = __float_as_uint(bs[cn * PITCH + kb + t]);
                b[nt][1] = __float_as_uint(bs[cn * PITCH + kb + t + 4]);
            }
#pragma unroll
            for (int mt = 0; mt < 4; mt++)
#pragma unroll
                for (int nt = 0; nt < 4; nt++)
                    MMA8(acc[mt][nt], a[mt], b[nt]);
        }
        __syncthreads();
        if (c + 2 < NCH) load(c + 2, c & 1);
    }

    // Epilogue: bias + scatter. c0,c1 -> (row g, cols 2t,2t+1); c2,c3 -> row g+8.
    const int hh = blockIdx.x;               // n-tile == one head (mode 0)
#pragma unroll
    for (int mt = 0; mt < 4; mt++) {
        int m = m0 + wm + mt * 16 + g;
        int bb = m >> 10, sp = m & 1023;
#pragma unroll
        for (int nt = 0; nt < 4; nt++) {
            int d = wn + nt * 8 + 2 * t;     // col within 128-wide tile
            int n = n0 + d;
            float b0v = __ldg(bias + n), b1v = __ldg(bias + n + 1);
            float2 v0 = make_float2(acc[mt][nt][0] + b0v, acc[mt][nt][1] + b1v);
            float2 v1 = make_float2(acc[mt][nt][2] + b0v, acc[mt][nt][3] + b1v);
            if (mode) {
                float* dst = outp + (size_t)m * DM + n;
                *(float2*)dst            = v0;
                *(float2*)(dst + 8 * DM) = v1;
            } else if (z == 0) {
                float* dst = g_q + ((size_t)(bb * NH + hh) * S_NEW + sp) * DK + d;
                *(float2*)dst            = v0;
                *(float2*)(dst + 8 * DK) = v1;
            } else {
                float* dst = cache_out
                    + ((size_t)(((z - 1) * BB + bb) * NH + hh) * S_TOT
                       + S_CACHE + sp) * DK + d;
                *(float2*)dst            = v0;
                *(float2*)(dst + 8 * DK) = v1;
            }
        }
    }
}

// ---------------------------------------------------------------------------
// 3) Causal flash attention (R6 passing version; epilogue RNA-rounds g_att).
// ---------------------------------------------------------------------------
#define FLASH_SMEM ((128*132 + 128*68 + 64*132 + 64*132) * 4)

__global__ __launch_bounds__(256, 1)
void flash_kernel(const float* __restrict__ cache_out) {
    extern __shared__ float smf[];
    float* Qs = smf;
    float* Ks = Qs + 128 * 132;
    float* Vs = Ks + 128 * 68;
    float* Ps = Vs + 64 * 132;

    const int qt = 7 - (int)blockIdx.x;
    const int h  = blockIdx.y;
    const int b  = blockIdx.z;
    const int q0 = qt << 7;
    const int tid = threadIdx.x;
    const int tx = tid & 15, ty = tid >> 4;

    const float* Qg = g_q + ((size_t)(b * NH + h) * S_NEW + q0) * DK;
    const float* Kg = cache_out + (size_t)(b * NH + h) * S_TOT * DK;
    const float* Vg = cache_out + (size_t)((BB + b) * NH + h) * S_TOT * DK;

#pragma unroll
    for (int it = 0; it < 16; ++it) {
        int id = tid + it * 256;
        int r  = id >> 5;
        int kc = (id & 31) << 2;
        float4 v = *(const float4*)(Qg + (size_t)r * DK + kc);
        Qs[(kc + 0) * 132 + r] = v.x;
        Qs[(kc + 1) * 132 + r] = v.y;
        Qs[(kc + 2) * 132 + r] = v.z;
        Qs[(kc + 3) * 132 + r] = v.w;
    }

    float Mrow[8], Lrow[8], O[8][8];
#pragma unroll
    for (int i = 0; i < 8; i++) {
        Mrow[i] = -1e30f; Lrow[i] = 0.f;
#pragma unroll
        for (int j = 0; j < 8; j++) O[i][j] = 0.f;
    }

    const float cs = 0.0883883476483184f * 1.4426950408889634f;
    const int ntiles = 50 + 2 * qt;

    for (int kt = 0; kt < ntiles; ++kt) {
        __syncthreads();
        const float* kp = Kg + (size_t)(kt * 64) * DK;
        const float* vp = Vg + (size_t)(kt * 64) * DK;
#pragma unroll
        for (int it = 0; it < 8; ++it) {
            int id = tid + it * 256;
            int n  = id >> 5;
            int kc = (id & 31) << 2;
            float4 kv4 = *(const float4*)(kp + (size_t)n * DK + kc);
            Ks[(kc + 0) * 68 + n] = kv4.x;
            Ks[(kc + 1) * 68 + n] = kv4.y;
            Ks[(kc + 2) * 68 + n] = kv4.z;
            Ks[(kc + 3) * 68 + n] = kv4.w;
            *(float4*)(Vs + n * 132 + kc) = *(const float4*)(vp + (size_t)n * DK + kc);
        }
        __syncthreads();

        float s[8][4];
#pragma unroll
        for (int i = 0; i < 8; i++)
#pragma unroll
            for (int j = 0; j < 4; j++) s[i][j] = 0.f;

#pragma unroll 4
        for (int k = 0; k < 128; k++) {
            float4 a0 = *(const float4*)(Qs + k * 132 + (ty << 3));
            float4 a1 = *(const float4*)(Qs + k * 132 + (ty << 3) + 4);
            float4 b4 = *(const float4*)(Ks + k * 68 + (tx << 2));
            float av[8] = {a0.x, a0.y, a0.z, a0.w, a1.x, a1.y, a1.z, a1.w};
            float bv[4] = {b4.x, b4.y, b4.z, b4.w};
#pragma unroll
            for (int i = 0; i < 8; i++)
#pragma unroll
                for (int j = 0; j < 4; j++) s[i][j] += av[i] * bv[j];
        }

        const bool domask = (kt * 64 + 63 >= S_CACHE + q0);
#pragma unroll
        for (int i = 0; i < 8; i++) {
            int m = (ty << 3) + i;
            float rmax = -1e30f;
#pragma unroll
            for (int j = 0; j < 4; j++) {
                float v = s[i][j] * cs;
                if (domask && (kt * 64 + (tx << 2) + j >= S_CACHE + q0 + m))
                    v = -1e30f;
                s[i][j] = v;
                rmax = fmaxf(rmax, v);
            }
            rmax = fmaxf(rmax, __shfl_xor_sync(0xffffffffu, rmax, 8));
            rmax = fmaxf(rmax, __shfl_xor_sync(0xffffffffu, rmax, 4));
            rmax = fmaxf(rmax, __shfl_xor_sync(0xffffffffu, rmax, 2));
            rmax = fmaxf(rmax, __shfl_xor_sync(0xffffffffu, rmax, 1));
            float newM  = fmaxf(Mrow[i], rmax);
            float alpha = exp2f(Mrow[i] - newM);
            Mrow[i] = newM;
            float rs = 0.f;
#pragma unroll
            for (int j = 0; j < 4; j++) {
                float p = exp2f(s[i][j] - newM);
                rs += p;
                Ps[((tx << 2) + j) * 132 + m] = p;
            }
            rs += __shfl_xor_sync(0xffffffffu, rs, 8);
            rs += __shfl_xor_sync(0xffffffffu, rs, 4);
            rs += __shfl_xor_sync(0xffffffffu, rs, 2);
            rs += __shfl_xor_sync(0xffffffffu, rs, 1);
            Lrow[i] = Lrow[i] * alpha + rs;
#pragma unroll
            for (int j = 0; j < 8; j++) O[i][j] *= alpha;
        }
        __syncthreads();

#pragma unroll 2
        for (int j = 0; j < 64; j++) {
            float4 p0 = *(const float4*)(Ps + j * 132 + (ty << 3));
            float4 p1 = *(const float4*)(Ps + j * 132 + (ty << 3) + 4);
            float4 v0 = *(const float4*)(Vs + j * 132 + (tx << 3));
            float4 v1 = *(const float4*)(Vs + j * 132 + (tx << 3) + 4);
            float pv[8] = {p0.x, p0.y, p0.z, p0.w, p1.x, p1.y, p1.z, p1.w};
            float vv[8] = {v0.x, v0.y, v0.z, v0.w, v1.x, v1.y, v1.z, v1.w};
#pragma unroll
            for (int i = 0; i < 8; i++)
#pragma unroll
                for (int d = 0; d < 8; d++) O[i][d] += pv[i] * vv[d];
        }
    }

    // normalize + RNA-round (A operand of out-proj) + write
#pragma unroll
    for (int i = 0; i < 8; i++) {
        float inv = 1.f / Lrow[i];
        int m = q0 + (ty << 3) + i;
        float* dst = g_att + (size_t)(b * S_NEW + m) * DM + h * DK + (tx << 3);
        float4 o0 = make_float4(rna_tf32(O[i][0] * inv), rna_tf32(O[i][1] * inv),
                                rna_tf32(O[i][2] * inv), rna_tf32(O[i][3] * inv));
        float4 o1 = make_float4(rna_tf32(O[i][4] * inv), rna_tf32(O[i][5] * inv),
                                rna_tf32(O[i][6] * inv), rna_tf32(O[i][7] * inv));
        *(float4*)dst       = o0;
        *(float4*)(dst + 4) = o1;
    }
}

// ---------------------------------------------------------------------------
// Launch
// ---------------------------------------------------------------------------
extern "C" void kernel_launch(void* const* d_in, const int* in_sizes, int n_in,
                              void* d_out, int out_size) {
    const float* x     = (const float*)d_in[0];
    const float* cache = (const float*)d_in[1];
    const float* Wq    = (const float*)d_in[2];
    const float* bq    = (const float*)d_in[3];
    const float* Wk    = (const float*)d_in[4];
    const float* bk    = (const float*)d_in[5];
    const float* Wv    = (const float*)d_in[6];
    const float* bv    = (const float*)d_in[7];
    const float* Wo    = (const float*)d_in[8];
    const float* bo    = (const float*)d_in[9];

    float* out       = (float*)d_out;
    float* cache_out = out + (size_t)BB * S_NEW * DM;

    // 0) round x + weights to tf32 (RNA)
    round_kernel<<<4096, 256>>>(x, Wq, Wk, Wv, Wo);

    // 1) copy old cache rows
    {
        int total  = 2 * BB * NH * (S_CACHE * DK / 4);
        int blocks = (total + 255) / 256;
        copy_cache_kernel<<<blocks, 256>>>((const float4*)cache, (float4*)cache_out);
    }

    // 2) fused QKV projections on tensor cores (z=0 Q, z=1 K, z=2 V)
    gemm_mma_kernel<<<dim3(16, 16, 3), 256>>>(bq, bk, bv, cache_out, nullptr, 0);

    // 3) flash attention (reads K/V from updated cache in d_out)
    cudaFuncSetAttribute(flash_kernel,
                         cudaFuncAttributeMaxDynamicSharedMemorySize, FLASH_SMEM);
    flash_kernel<<<dim3(8, NH, BB), 256, FLASH_SMEM>>>(cache_out);

    // 4) output projection on tensor cores
    gemm_mma_kernel<<<dim3(16, 16, 1), 256>>>(bo, nullptr, nullptr,
                                              nullptr, out, 1);
}

// round 12
// speedup vs baseline: 3.3923x; 2.0999x over previous
#include <cuda_runtime.h>
#include <cstdint>

// Problem constants
#define BB      2
#define S_NEW   1024
#define S_CACHE 3072
#define S_TOT   4096
#define NH      16
#define DK      128
#define DM      2048

// Scratch (device globals — no allocation allowed)
__device__ float g_q[BB*NH*S_NEW*DK];    // Q in [b,h,s,d] (tf32-rounded)
__device__ float g_att[BB*S_NEW*DM];     // attention output [b,s,h*dk] (tf32-rounded)
__device__ float g_xr[BB*S_NEW*DM];      // x rounded to tf32
__device__ float g_wr[4*DM*DM];          // Wq,Wk,Wv,Wo rounded to tf32

// ---------------------------------------------------------------------------
// helpers
// ---------------------------------------------------------------------------
__device__ __forceinline__ uint32_t smem_u32(const void* p) {
    uint32_t a;
    asm("{ .reg .u64 t; cvta.to.shared.u64 t, %1; cvt.u32.u64 %0, t; }"
        : "=r"(a) : "l"(p));
    return a;
}
__device__ __forceinline__ void cp16(uint32_t so, const void* gp) {
    asm volatile("cp.async.cg.shared.global [%0], [%1], 16;" :: "r"(so), "l"(gp));
}
__device__ __forceinline__ float rna_tf32(float x) {
    uint32_t u;
    asm("cvt.rna.tf32.f32 %0, %1;" : "=r"(u) : "f"(x));
    return __uint_as_float(u);
}

// D(16x8) += A(16x8,row) * B(8x8,col)  — tf32 tensor-core MMA (baseline PTX)
#define MMA8(c, a, b)                                                          \
    asm volatile("mma.sync.aligned.m16n8k8.row.col.f32.tf32.tf32.f32 "        \
        "{%0,%1,%2,%3}, {%4,%5,%6,%7}, {%8,%9}, {%0,%1,%2,%3};"               \
        : "+f"((c)[0]), "+f"((c)[1]), "+f"((c)[2]), "+f"((c)[3])              \
        : "r"((a)[0]), "r"((a)[1]), "r"((a)[2]), "r"((a)[3]),                 \
          "r"((b)[0]), "r"((b)[1]))

// ---------------------------------------------------------------------------
// 0) Round x and the four weight matrices to tf32 (RNA, unbiased) once.
// ---------------------------------------------------------------------------
__global__ void round_kernel(const float* __restrict__ x,
                             const float* __restrict__ Wq,
                             const float* __restrict__ Wk,
                             const float* __restrict__ Wv,
                             const float* __restrict__ Wo) {
    const int SEG = DM * DM;                 // 4194304
    int i = blockIdx.x * blockDim.x + threadIdx.x;
    const int stride = gridDim.x * blockDim.x;
    for (; i < 5 * SEG; i += stride) {
        int seg = i >> 22, o = i & (SEG - 1);
        float v;
        float* dst;
        if (seg == 0)      { v = x[o];  dst = g_xr + o; }
        else               { const float* W = (seg == 1) ? Wq : (seg == 2) ? Wk
                                              : (seg == 3) ? Wv : Wo;
                             v = W[o]; dst = g_wr + (size_t)(seg - 1) * SEG + o; }
        *dst = rna_tf32(v);
    }
}

// ---------------------------------------------------------------------------
// 1) Copy old cache rows into the updated-cache output region
// ---------------------------------------------------------------------------
__global__ void copy_cache_kernel(const float4* __restrict__ src,
                                  float4* __restrict__ dst) {
    int i = blockIdx.x * blockDim.x + threadIdx.x;
    const int per   = S_CACHE * DK / 4;
    const int total = 2 * BB * NH * per;
    if (i < total) {
        int c = i / per;
        int w = i - c * per;
        dst[(size_t)c * (S_TOT * DK / 4) + w] = src[i];
    }
}

// ---------------------------------------------------------------------------
// 2/4) Tensor-core GEMM (mma.sync tf32): Y[M,N] = A[M,K] @ W[N,K]^T + bias.
// ---------------------------------------------------------------------------
#define KC    16
#define PITCH 20
#define NCH   (DM / KC)          // 128

__global__ __launch_bounds__(256, 2)
void gemm_mma_kernel(const float* __restrict__ B0,
                     const float* __restrict__ B1,
                     const float* __restrict__ B2,
                     float* __restrict__ cache_out,
                     float* __restrict__ outp,
                     int mode) {
    __shared__ __align__(16) float As[2][128 * PITCH];
    __shared__ __align__(16) float Bs[2][128 * PITCH];

    const int tid = threadIdx.x;
    const int warp = tid >> 5, lane = tid & 31;
    const int g = lane >> 2, t = lane & 3;
    const int z = blockIdx.z;

    const float* Ap = mode ? g_att : g_xr;
    const float* W  = g_wr + (size_t)(mode ? 3 : z) * DM * DM;
    const float* bias = mode ? B0 : (z == 0 ? B0 : (z == 1 ? B1 : B2));

    const int m0 = blockIdx.y * 128, n0 = blockIdx.x * 128;
    const int wm = (warp & 1) * 64, wn = (warp >> 1) * 32;

    const uint32_t sA = smem_u32(As);
    const uint32_t sB = smem_u32(Bs);

    float acc[4][4][4];
#pragma unroll
    for (int mt = 0; mt < 4; mt++)
#pragma unroll
        for (int nt = 0; nt < 4; nt++)
#pragma unroll
            for (int r = 0; r < 4; r++) acc[mt][nt][r] = 0.f;

    auto load = [&](int c, int buf) {
        const int k0 = c * KC;
        const uint32_t off = (uint32_t)buf * 128 * PITCH * 4;
#pragma unroll
        for (int i = 0; i < 2; i++) {
            int idx = tid + i * 256;
            int row = idx >> 2, c4 = idx & 3;
            cp16(sA + off + (row * PITCH + c4 * 4) * 4,
                 Ap + (size_t)(m0 + row) * DM + k0 + c4 * 4);
            cp16(sB + off + (row * PITCH + c4 * 4) * 4,
                 W + (size_t)(n0 + row) * DM + k0 + c4 * 4);
        }
        asm volatile("cp.async.commit_group;" ::: "memory");
    };

    load(0, 0);
    load(1, 1);

    for (int c = 0; c < NCH; ++c) {
        if (c + 1 < NCH) asm volatile("cp.async.wait_group 1;" ::: "memory");
        else             asm volatile("cp.async.wait_group 0;" ::: "memory");
        __syncthreads();

        const float* as = As[c & 1];
        const float* bs = Bs[c & 1];
#pragma unroll
        for (int ks = 0; ks < 2; ks++) {
            const int kb = ks * 8;
            uint32_t a[4][4], b[4][2];
#pragma unroll
            for (int mt = 0; mt < 4; mt++) {
                int r = wm + mt * 16 + g;
                a[mt][0] = __float_as_uint(as[r * PITCH + kb + t]);
                a[mt][1] = __float_as_uint(as[(r + 8) * PITCH + kb + t]);
                a[mt][2] = __float_as_uint(as[r * PITCH + kb + t + 4]);
                a[mt][3] = __float_as_uint(as[(r + 8) * PITCH + kb + t + 4]);
            }
#pragma unroll
            for (int nt = 0; nt < 4; nt++) {
                int cn = wn + nt * 8 + g;
                b[nt][0] = __float_as_uint(bs[cn * PITCH + kb + t]);
                b[nt][1] = __float_as_uint(bs[cn * PITCH + kb + t + 4]);
            }
#pragma unroll
            for (int mt = 0; mt < 4; mt++)
#pragma unroll
                for (int nt = 0; nt < 4; nt++)
                    MMA8(acc[mt][nt], a[mt], b[nt]);
        }
        __syncthreads();
        if (c + 2 < NCH) load(c + 2, c & 1);
    }

    const int hh = blockIdx.x;
#pragma unroll
    for (int mt = 0; mt < 4; mt++) {
        int m = m0 + wm + mt * 16 + g;
        int bb = m >> 10, sp = m & 1023;
#pragma unroll
        for (int nt = 0; nt < 4; nt++) {
            int d = wn + nt * 8 + 2 * t;
            int n = n0 + d;
            float b0v = __ldg(bias + n), b1v = __ldg(bias + n + 1);
            float2 v0 = make_float2(acc[mt][nt][0] + b0v, acc[mt][nt][1] + b1v);
            float2 v1 = make_float2(acc[mt][nt][2] + b0v, acc[mt][nt][3] + b1v);
            if (mode) {
                float* dst = outp + (size_t)m * DM + n;
                *(float2*)dst            = v0;
                *(float2*)(dst + 8 * DM) = v1;
            } else if (z == 0) {
                // Q: RNA-round so the attention MMA truncation is unbiased
                v0.x = rna_tf32(v0.x); v0.y = rna_tf32(v0.y);
                v1.x = rna_tf32(v1.x); v1.y = rna_tf32(v1.y);
                float* dst = g_q + ((size_t)(bb * NH + hh) * S_NEW + sp) * DK + d;
                *(float2*)dst            = v0;
                *(float2*)(dst + 8 * DK) = v1;
            } else {
                float* dst = cache_out
                    + ((size_t)(((z - 1) * BB + bb) * NH + hh) * S_TOT
                       + S_CACHE + sp) * DK + d;
                *(float2*)dst            = v0;
                *(float2*)(dst + 8 * DK) = v1;
            }
        }
    }
}

// ---------------------------------------------------------------------------
// 3) Causal flash attention on tensor cores (mma.sync tf32).
//    One block = (b, h, 128-query tile); 8 warps x 16 rows; 64-key tiles.
//    Qs[m][k], Ks[n][k] natural (row.col MMA); Vt[d][j] transposed; Ps[m][j].
// ---------------------------------------------------------------------------
#define FL_SMEM ((128*132 + 64*132 + 128*68 + 128*68) * 4)   // 171008 B

__global__ __launch_bounds__(256, 1)
void flash_mma_kernel(const float* __restrict__ cache_out) {
    extern __shared__ float smf[];
    float* Qs = smf;                    // [128][132]
    float* Ks = Qs + 128 * 132;         // [64][132]
    float* Vt = Ks + 64 * 132;          // [128][68]
    float* Ps = Vt + 128 * 68;          // [128][68]

    const int qt = 7 - (int)blockIdx.x;      // longest tiles first
    const int h  = blockIdx.y;
    const int b  = blockIdx.z;
    const int q0 = qt << 7;
    const int tid  = threadIdx.x;
    const int warp = tid >> 5, lane = tid & 31;
    const int g = lane >> 2, t = lane & 3;
    const int wm = warp << 4;

    const float* Qg = g_q + ((size_t)(b * NH + h) * S_NEW + q0) * DK;
    const float* Kg = cache_out + (size_t)(b * NH + h) * S_TOT * DK;
    const float* Vg = cache_out + (size_t)((BB + b) * NH + h) * S_TOT * DK;

    const uint32_t sQ = smem_u32(Qs), sK = smem_u32(Ks);

    // Q tile via cp.async (128x128)
#pragma unroll
    for (int i = 0; i < 16; i++) {
        int idx = tid + i * 256;         // 0..4095
        int row = idx >> 5, c16 = idx & 31;
        cp16(sQ + (row * 132 + c16 * 4) * 4, Qg + (size_t)row * DK + c16 * 4);
    }
    asm volatile("cp.async.commit_group;" ::: "memory");

    float O[16][4];
    float M[2] = {-1e30f, -1e30f}, L[2] = {0.f, 0.f};
#pragma unroll
    for (int i = 0; i < 16; i++) { O[i][0] = O[i][1] = O[i][2] = O[i][3] = 0.f; }

    const float cs = 0.0883883476483184f * 1.4426950408889634f; // 1/sqrt(128)*log2e
    const int ntiles = 50 + 2 * qt;

    for (int kt = 0; kt < ntiles; ++kt) {
        __syncthreads();                 // prior Ks/Vt fully consumed
        const float* kp = Kg + (size_t)(kt * 64) * DK;
        const float* vp = Vg + (size_t)(kt * 64) * DK;

        // K tile (64x128) natural layout via cp.async
#pragma unroll
        for (int i = 0; i < 8; i++) {
            int idx = tid + i * 256;     // 0..2047
            int row = idx >> 5, c16 = idx & 31;
            cp16(sK + (row * 132 + c16 * 4) * 4, kp + (size_t)row * DK + c16 * 4);
        }
        asm volatile("cp.async.commit_group;" ::: "memory");

        // V transposed: Vt[d][j]. Coalesced LDG.32 per j, STS.128 per d-row.
#pragma unroll
        for (int i = 0; i < 8; i++) {
            int idx = tid + i * 256;     // 0..2047
            int d = idx & 127, j0 = (idx >> 7) << 2;
            float4 v;
            v.x = vp[(size_t)(j0 + 0) * DK + d];
            v.y = vp[(size_t)(j0 + 1) * DK + d];
            v.z = vp[(size_t)(j0 + 2) * DK + d];
            v.w = vp[(size_t)(j0 + 3) * DK + d];
            *(float4*)(Vt + d * 68 + j0) = v;
        }
        asm volatile("cp.async.wait_group 0;" ::: "memory");
        __syncthreads();

        // ---- S = Q @ K^T (warp: 16x64) ----
        float s[8][4];
#pragma unroll
        for (int nt = 0; nt < 8; nt++) { s[nt][0] = s[nt][1] = s[nt][2] = s[nt][3] = 0.f; }
#pragma unroll
        for (int ks = 0; ks < 16; ks++) {
            const int kb = ks * 8;
            uint32_t a[4];
            a[0] = __float_as_uint(Qs[(wm + g) * 132 + kb + t]);
            a[1] = __float_as_uint(Qs[(wm + g + 8) * 132 + kb + t]);
            a[2] = __float_as_uint(Qs[(wm + g) * 132 + kb + t + 4]);
            a[3] = __float_as_uint(Qs[(wm + g + 8) * 132 + kb + t + 4]);
#pragma unroll
            for (int nt = 0; nt < 8; nt++) {
                uint32_t bf[2];
                bf[0] = __float_as_uint(Ks[(nt * 8 + g) * 132 + kb + t]);
                bf[1] = __float_as_uint(Ks[(nt * 8 + g) * 132 + kb + t + 4]);
                MMA8(s[nt], a, bf);
            }
        }

        // ---- online softmax (rows g, g+8 of this warp) ----
        const bool domask = (kt * 64 + 63 >= S_CACHE + q0);
#pragma unroll
        for (int r = 0; r < 2; r++) {
            const int ml = wm + g + 8 * r;       // query row within tile
            float mx = -1e30f;
#pragma unroll
            for (int nt = 0; nt < 8; nt++) {
                float v0 = s[nt][2 * r]     * cs;
                float v1 = s[nt][2 * r + 1] * cs;
                if (domask) {
                    int j = kt * 64 + nt * 8 + 2 * t;
                    if (j     >= S_CACHE + q0 + ml) v0 = -1e30f;
                    if (j + 1 >= S_CACHE + q0 + ml) v1 = -1e30f;
                }
                s[nt][2 * r] = v0; s[nt][2 * r + 1] = v1;
                mx = fmaxf(mx, fmaxf(v0, v1));
            }
            mx = fmaxf(mx, __shfl_xor_sync(0xffffffffu, mx, 1));
            mx = fmaxf(mx, __shfl_xor_sync(0xffffffffu, mx, 2));
            float newM  = fmaxf(M[r], mx);
            float alpha = exp2f(M[r] - newM);
            M[r] = newM;
            float rs = 0.f;
#pragma unroll
            for (int nt = 0; nt < 8; nt++) {
                float p0 = rna_tf32(exp2f(s[nt][2 * r]     - newM));
                float p1 = rna_tf32(exp2f(s[nt][2 * r + 1] - newM));
                rs += p0 + p1;
                *(float2*)(Ps + ml * 68 + nt * 8 + 2 * t) = make_float2(p0, p1);
            }
            rs += __shfl_xor_sync(0xffffffffu, rs, 1);
            rs += __shfl_xor_sync(0xffffffffu, rs, 2);
            L[r] = L[r] * alpha + rs;
#pragma unroll
            for (int dt = 0; dt < 16; dt++) {
                O[dt][2 * r]     *= alpha;
                O[dt][2 * r + 1] *= alpha;
            }
        }
        __syncwarp();

        // ---- O += P @ V (warp: 16x128, k=64) ----
#pragma unroll
        for (int jb = 0; jb < 8; jb++) {
            const int kb = jb * 8;
            uint32_t a[4];
            a[0] = __float_as_uint(Ps[(wm + g) * 68 + kb + t]);
            a[1] = __float_as_uint(Ps[(wm + g + 8) * 68 + kb + t]);
            a[2] = __float_as_uint(Ps[(wm + g) * 68 + kb + t + 4]);
            a[3] = __float_as_uint(Ps[(wm + g + 8) * 68 + kb + t + 4]);
#pragma unroll
            for (int dt = 0; dt < 16; dt++) {
                uint32_t bf[2];
                bf[0] = __float_as_uint(Vt[(dt * 8 + g) * 68 + kb + t]);
                bf[1] = __float_as_uint(Vt[(dt * 8 + g) * 68 + kb + t + 4]);
                MMA8(O[dt], a, bf);
            }
        }
    }

    // epilogue: normalize + RNA-round + write g_att [b,s,h*dk]
#pragma unroll
    for (int r = 0; r < 2; r++) {
        float inv = 1.f / L[r];
        int m = q0 + wm + g + 8 * r;
        float* dst = g_att + (size_t)(b * S_NEW + m) * DM + h * DK;
#pragma unroll
        for (int dt = 0; dt < 16; dt++) {
            float2 v = make_float2(rna_tf32(O[dt][2 * r] * inv),
                                   rna_tf32(O[dt][2 * r + 1] * inv));
            *(float2*)(dst + dt * 8 + 2 * t) = v;
        }
    }
}

// ---------------------------------------------------------------------------
// Launch
// ---------------------------------------------------------------------------
extern "C" void kernel_launch(void* const* d_in, const int* in_sizes, int n_in,
                              void* d_out, int out_size) {
    const float* x     = (const float*)d_in[0];
    const float* cache = (const float*)d_in[1];
    const float* Wq    = (const float*)d_in[2];
    const float* bq    = (const float*)d_in[3];
    const float* Wk    = (const float*)d_in[4];
    const float* bk    = (const float*)d_in[5];
    const float* Wv    = (const float*)d_in[6];
    const float* bv    = (const float*)d_in[7];
    const float* Wo    = (const float*)d_in[8];
    const float* bo    = (const float*)d_in[9];

    float* out       = (float*)d_out;
    float* cache_out = out + (size_t)BB * S_NEW * DM;

    // 0) round x + weights to tf32 (RNA)
    round_kernel<<<4096, 256>>>(x, Wq, Wk, Wv, Wo);

    // 1) copy old cache rows
    {
        int total  = 2 * BB * NH * (S_CACHE * DK / 4);
        int blocks = (total + 255) / 256;
        copy_cache_kernel<<<blocks, 256>>>((const float4*)cache, (float4*)cache_out);
    }

    // 2) fused QKV projections on tensor cores (z=0 Q, z=1 K, z=2 V)
    gemm_mma_kernel<<<dim3(16, 16, 3), 256>>>(bq, bk, bv, cache_out, nullptr, 0);

    // 3) flash attention on tensor cores
    cudaFuncSetAttribute(flash_mma_kernel,
                         cudaFuncAttributeMaxDynamicSharedMemorySize, FL_SMEM);
    flash_mma_kernel<<<dim3(8, NH, BB), 256, FL_SMEM>>>(cache_out);

    // 4) output projection on tensor cores
    gemm_mma_kernel<<<dim3(16, 16, 1), 256>>>(bo, nullptr, nullptr,
                                              nullptr, out, 1);
}